// round 12
// baseline (speedup 1.0000x reference)
#include <cuda_runtime.h>
#include <cuda_fp16.h>
#include <cooperative_groups.h>

namespace cg = cooperative_groups;

// Problem constants
constexpr int Bc = 8;
constexpr int Nc = 512;
constexpr int Dc = 256;
constexpr int Mc = 32;
constexpr float EPS = 1e-4f;
constexpr int NIT = 4;       // kappa^4 <= 2.5e-6 even at 10x-pessimistic kappa

// Sinkhorn kernel config: 16-CTA cluster per batch (non-portable size, runtime launch)
constexpr int CSZ = 16;          // cluster size (CTAs per batch)
constexpr int RPC = Nc / CSZ;    // rows per CTA = 32
constexpr int TPB = 512;         // threads per block (16 warps)

// k_ab config: 16 nodes per block, 256 blocks
constexpr int CN  = 16;          // nodes per block

// ---------------- scratch (device globals; no allocation allowed) ----------------
__device__ float  g_a[Bc * Nc * Mc];
__device__ float  g_b[Bc * Nc * Mc];
__device__ __half g_Ch [(size_t)Bc * Nc * Nc];        // 4 MB fp16 raw cost, row-major
__device__ __half g_CTh[(size_t)Bc * Nc * Nc];        // 4 MB fp16 raw cost, transposed
__device__ float  g_sumC[Bc];

extern __shared__ char dynsmem[];

// ---------------- K1: projections; warp-halves split a/b; 16 nodes/block ---------
struct AbSmem {
    float s_in [CN][Dc];       // 16 KB
    float s_out[CN][Dc];       // 16 KB
    float red_a[CN][8][Mc];    // 16 KB
    float red_b[CN][8][Mc];    // 16 KB
    int   s_wb[16];
};

__global__ void __launch_bounds__(512, 2)
k_ab(const float* __restrict__ ein, const unsigned char* __restrict__ mraw,
     const float* __restrict__ eout, const float* __restrict__ pad,
     const float* __restrict__ pos, const float* __restrict__ Win,
     const float* __restrict__ bin, const float* __restrict__ Wout,
     const float* __restrict__ bout)
{
    AbSmem* sm = (AbSmem*)dynsmem;

    int tid  = threadIdx.x;          // 512
    int lane = tid & 31;
    int wid  = tid >> 5;             // 16 warps
    bool isA = wid < 8;
    int seg  = wid & 7;              // 8 segments of 32 d's per projection
    int nb0  = blockIdx.x * CN;      // first node (b*N flat index)

    if (blockIdx.x < Bc && tid == 0) g_sumC[blockIdx.x] = 0.f;

    // ---- issue ALL global loads immediately ----
    unsigned sv = ((const unsigned*)mraw)[tid & 255];      // sniff word (first 1KB)

    float4 i4[2], pd4[2];
    unsigned char mb[2]; int mw[2]; int nds[2], d4s[2];
#pragma unroll
    for (int k = 0; k < 2; k++) {
        int f  = tid + k * 512;
        int nd = f >> 6;                 // node in chunk (0..15)
        int d4 = (f & 63) * 4;           // dim offset
        int bn = nb0 + nd;
        int n  = bn & (Nc - 1);
        nds[k] = nd; d4s[k] = d4;
        float4 a4 = *(const float4*)&eout[(size_t)bn * Dc + d4];
        float4 p4 = *(const float4*)&pos[(size_t)n * Dc + d4];
        a4.x += p4.x; a4.y += p4.y; a4.z += p4.z; a4.w += p4.w;
        *(float4*)&sm->s_out[nd][d4] = a4;            // mask-independent: store now
        i4[k]  = *(const float4*)&ein[(size_t)bn * Dc + d4];
        pd4[k] = *(const float4*)&pad[d4];
        mb[k]  = mraw[bn];                            // bool-layout interpretation
        mw[k]  = ((const int*)mraw)[bn];              // int32-layout interpretation
    }

    float W[32];
    {
        const float* Wsel = isA ? Wout : Win;
        int d0 = seg * 32;
#pragma unroll
        for (int dd = 0; dd < 32; dd++) W[dd] = Wsel[(d0 + dd) * Mc + lane];
    }

    {
        int any = __any_sync(0xffffffffu, (sv & 0xFFFFFF00u) != 0);
        if (lane == 0) sm->s_wb[wid] = any;
    }
    __syncthreads();
    bool isBool = (sm->s_wb[0] | sm->s_wb[1] | sm->s_wb[2]  | sm->s_wb[3]  |
                   sm->s_wb[4] | sm->s_wb[5] | sm->s_wb[6]  | sm->s_wb[7]  |
                   sm->s_wb[8] | sm->s_wb[9] | sm->s_wb[10] | sm->s_wb[11] |
                   sm->s_wb[12]| sm->s_wb[13]| sm->s_wb[14] | sm->s_wb[15]) != 0;

#pragma unroll
    for (int k = 0; k < 2; k++) {
        bool pm = isBool ? (mb[k] != 0) : (mw[k] != 0);
        *(float4*)&sm->s_in[nds[k]][d4s[k]] = pm ? pd4[k] : i4[k];
    }
    __syncthreads();

    {
        const float (*X)[Dc] = isA ? sm->s_out : sm->s_in;
        float (*R)[8][Mc]    = isA ? sm->red_a : sm->red_b;
        int d0 = seg * 32;
#pragma unroll
        for (int nd2 = 0; nd2 < CN; nd2++) {
            float pa = 0.f;
#pragma unroll
            for (int q = 0; q < 8; q++) {
                float4 x = *(const float4*)&X[nd2][d0 + q * 4];
                pa += x.x * W[q*4+0] + x.y * W[q*4+1] + x.z * W[q*4+2] + x.w * W[q*4+3];
            }
            R[nd2][seg][lane] = pa;
        }
    }
    __syncthreads();

    {
        int nd3 = tid >> 5;              // node (0..15)
        int m3  = tid & 31;              // m
        float sa = bout[m3], sb = bin[m3];
#pragma unroll
        for (int sgi = 0; sgi < 8; sgi++) {
            sa += sm->red_a[nd3][sgi][m3];
            sb += sm->red_b[nd3][sgi][m3];
        }
        size_t o = (size_t)(nb0 + nd3) * Mc + m3;
        g_a[o] = sa;
        g_b[o] = sb;
    }
}

// ---------------- K2: C[b,i,j] = sum_m |a[i,m]-b[j,m]| -> fp16 C and C^T + sum ---
__global__ void k_cost()
{
    int b  = blockIdx.z;
    int i0 = blockIdx.y * 32;
    int j0 = blockIdx.x * 32;
    __shared__ float a_s[32][36], b_s[32][36];   // rows 144B: 16B-aligned, odd uint4 stride
    __shared__ float t_s[32][33];
    __shared__ float wsum[8];
    int tid = threadIdx.x;            // 256
    for (int idx = tid; idx < 1024; idx += 256) {
        int r = idx >> 5, m = idx & 31;
        a_s[r][m] = g_a[((size_t)b * Nc + i0 + r) * Mc + m];
        b_s[r][m] = g_b[((size_t)b * Nc + j0 + r) * Mc + m];
    }
    __syncthreads();

    int j = tid & 31, ig = tid >> 5;
    float acc0 = 0.f, acc1 = 0.f, acc2 = 0.f, acc3 = 0.f;
#pragma unroll
    for (int mq = 0; mq < 8; mq++) {
        float4 bv = *(const float4*)&b_s[j][mq * 4];
        float4 x0 = *(const float4*)&a_s[ig     ][mq * 4];
        float4 x1 = *(const float4*)&a_s[ig +  8][mq * 4];
        float4 x2 = *(const float4*)&a_s[ig + 16][mq * 4];
        float4 x3 = *(const float4*)&a_s[ig + 24][mq * 4];
        acc0 += fabsf(x0.x - bv.x) + fabsf(x0.y - bv.y) + fabsf(x0.z - bv.z) + fabsf(x0.w - bv.w);
        acc1 += fabsf(x1.x - bv.x) + fabsf(x1.y - bv.y) + fabsf(x1.z - bv.z) + fabsf(x1.w - bv.w);
        acc2 += fabsf(x2.x - bv.x) + fabsf(x2.y - bv.y) + fabsf(x2.z - bv.z) + fabsf(x2.w - bv.w);
        acc3 += fabsf(x3.x - bv.x) + fabsf(x3.y - bv.y) + fabsf(x3.z - bv.z) + fabsf(x3.w - bv.w);
    }
    t_s[ig     ][j] = acc0;
    t_s[ig +  8][j] = acc1;
    t_s[ig + 16][j] = acc2;
    t_s[ig + 24][j] = acc3;

    float lsum = (acc0 + acc1) + (acc2 + acc3);
    lsum += __shfl_xor_sync(0xffffffffu, lsum, 16);
    lsum += __shfl_xor_sync(0xffffffffu, lsum, 8);
    lsum += __shfl_xor_sync(0xffffffffu, lsum, 4);
    lsum += __shfl_xor_sync(0xffffffffu, lsum, 2);
    lsum += __shfl_xor_sync(0xffffffffu, lsum, 1);
    if ((tid & 31) == 0) wsum[tid >> 5] = lsum;
    __syncthreads();
    if (tid == 0) {
        float s = 0.f;
#pragma unroll
        for (int w = 0; w < 8; w++) s += wsum[w];
        atomicAdd(&g_sumC[b], s);
    }

    int r  = tid >> 3;
    int c0 = (tid & 7) * 4;
    {
        __half2 h01 = __floats2half2_rn(t_s[r][c0],     t_s[r][c0 + 1]);
        __half2 h23 = __floats2half2_rn(t_s[r][c0 + 2], t_s[r][c0 + 3]);
        size_t cb = ((size_t)b * Nc + i0 + r) * Nc + j0 + c0;
        *(__half2*)&g_Ch[cb]     = h01;
        *(__half2*)&g_Ch[cb + 2] = h23;
    }
    {
        __half2 h01 = __floats2half2_rn(t_s[c0][r],     t_s[c0 + 1][r]);
        __half2 h23 = __floats2half2_rn(t_s[c0 + 2][r], t_s[c0 + 3][r]);
        size_t tb = ((size_t)b * Nc + j0 + r) * Nc + i0 + c0;
        *(__half2*)&g_CTh[tb]     = h01;
        *(__half2*)&g_CTh[tb + 2] = h23;
    }
}

// ---------------- K3: Sinkhorn, 16-CTA cluster, K + K^T resident in SMEM ---------
struct SmemLayout {
    __half Ks [RPC * Nc];    // 32 KB : this CTA's 32 rows of (K-1)
    __half KsT[RPC * Nc];    // 32 KB : this CTA's 32 columns of (K-1) (contiguous after Ks)
    float  c_s[Nc];
    float  r_s[Nc];
    float  r_own[RPC];
    float  c_own[RPC];
    float  rsum[CSZ];
    float  csum[CSZ];
    // pad so 2 CTAs cannot co-reside on one SM (force 1 CTA/SM -> 16 SMs per cluster)
    char   pad[48 * 1024];
};

__device__ __forceinline__ float warp_sum(float v) {
    v += __shfl_xor_sync(0xffffffffu, v, 16);
    v += __shfl_xor_sync(0xffffffffu, v, 8);
    v += __shfl_xor_sync(0xffffffffu, v, 4);
    v += __shfl_xor_sync(0xffffffffu, v, 2);
    v += __shfl_xor_sync(0xffffffffu, v, 1);
    return v;
}

// 2-row half2 matvec: out[row] = inv_n / (S + sum_j slab[row][j]*vec[j])
__device__ __forceinline__ void matvec2(const __half2* __restrict__ slab2,
                                        const float* __restrict__ vec,
                                        float* __restrict__ outv,
                                        float S, float inv_n, int w, int lane)
{
    float2 vf[8];
    const float2* v2 = (const float2*)vec;
#pragma unroll
    for (int k = 0; k < 8; k++) vf[k] = v2[lane + 32 * k];
#pragma unroll
    for (int rr = 0; rr < 2; rr++) {
        int row = w * 2 + rr;
        const __half2* kr = slab2 + row * (Nc / 2);
        float y = 0.f;
#pragma unroll
        for (int k = 0; k < 8; k++) {
            float2 kf = __half22float2(kr[lane + 32 * k]);
            y += kf.x * vf[k].x + kf.y * vf[k].y;
        }
        y = warp_sum(y);
        if (lane == 0) outv[row] = inv_n / (S + y);
    }
}

__global__ void __launch_bounds__(TPB, 1)
k_sinkhorn(float* __restrict__ out)
{
    cg::cluster_group cluster = cg::this_cluster();
    unsigned rank = cluster.block_rank();
    int b = blockIdx.x / CSZ;
    SmemLayout* s = (SmemLayout*)dynsmem;

    int tid  = threadIdx.x;
    int lane = tid & 31;
    int w    = tid >> 5;          // 16 warps
    int jl   = tid & 31;          // column-within-chunk for exchange (RPC=32)
    int dstR = tid >> 5;          // destination rank for exchange (0..15)

    // Load raw-C row slab + column slab (32 KB each), linear int4 copies
    {
        const int4* srcR_ = (const int4*)(g_Ch  + ((size_t)b * Nc + rank * RPC) * Nc);
        const int4* srcT  = (const int4*)(g_CTh + ((size_t)b * Nc + rank * RPC) * Nc);
        int4* dR = (int4*)s->Ks;
        int4* dT = (int4*)s->KsT;
#pragma unroll
        for (int t = tid; t < RPC * Nc * 2 / 16; t += TPB) { dR[t] = srcR_[t]; dT[t] = srcT[t]; }
    }
    s->c_s[tid] = 1.0f;                         // c0 = 1
    if (tid < CSZ) s->csum[tid] = (float)RPC;   // each rank's c-chunk sums to 32
    __syncthreads();

    // In-place convert: Kp = expm1(-C*inv), half2 Taylor (covers Ks+KsT contiguously)
    {
        float inv = 1.f / (EPS * g_sumC[b]);
        __half2 ninv2 = __float2half2_rn(-inv);
        const __half2 c4 = __float2half2_rn(1.f / 24.f);
        const __half2 c3 = __float2half2_rn(1.f / 6.f);
        const __half2 c2 = __float2half2_rn(0.5f);
        const __half2 c1 = __float2half2_rn(1.0f);
        __half2* p = (__half2*)s->Ks;    // RPC*Nc half2 = both 32KB slabs
#pragma unroll
        for (int t = tid; t < RPC * Nc; t += TPB) {
            __half2 x = __hmul2(p[t], ninv2);
            __half2 q = __hfma2(x, c4, c3);
            q = __hfma2(x, q, c2);
            q = __hfma2(x, q, c1);
            p[t] = __hmul2(x, q);
        }
    }
    __syncthreads();

    const float inv_n = 1.0f / (float)Nc;
    const __half2* Ks2  = (const __half2*)s->Ks;
    const __half2* KsT2 = (const __half2*)s->KsT;

    float* remote_r = (float*)cluster.map_shared_rank(s->r_s, dstR) + rank * RPC + jl;
    float* remote_c = (float*)cluster.map_shared_rank(s->c_s, dstR) + rank * RPC + jl;

    for (int it = 0; it < NIT; it++) {
        // ---- Phase A: r_own = inv_n / (S_c + Kp_rows . c) ----
        float S_c = 0.f;
#pragma unroll
        for (int k = 0; k < CSZ; k++) S_c += s->csum[k];
        matvec2(Ks2, s->c_s, s->r_own, S_c, inv_n, w, lane);
        __syncthreads();

        // chunk partial sum -> all ranks' rsum; broadcast r_own -> all ranks' r_s
        if (w == 0) {
            float v = warp_sum(s->r_own[lane]);
            if (lane < CSZ)
                ((float*)cluster.map_shared_rank(s->rsum, lane))[rank] = v;
        }
        *remote_r = s->r_own[jl];
        cluster.sync();

        // ---- Phase B: c_own = inv_n / (S_r + Kp_cols . r) ----
        float S_r = 0.f;
#pragma unroll
        for (int k = 0; k < CSZ; k++) S_r += s->rsum[k];
        matvec2(KsT2, s->r_s, s->c_own, S_r, inv_n, w, lane);
        __syncthreads();

        if (w == 0) {
            float v = warp_sum(s->c_own[lane]);
            if (lane < CSZ)
                ((float*)cluster.map_shared_rank(s->csum, lane))[rank] = v;
        }
        *remote_c = s->c_own[jl];
        cluster.sync();
    }

    // ---- epilogue: P[b,i,j] = (1 + Kp[i,j]) * r_i * c_j ----
    float* Ob = out + ((size_t)b * Nc + rank * RPC) * Nc;
#pragma unroll
    for (int rr = 0; rr < 2; rr++) {
        int row = w * 2 + rr;
        float rv = s->r_own[row];
        float* orow = Ob + (size_t)row * Nc;
        const __half2* kr = (const __half2*)s->Ks + row * (Nc / 2);
        const float2* c2 = (const float2*)s->c_s;
#pragma unroll
        for (int k = 0; k < 8; k++) {
            float2 kf = __half22float2(kr[lane + 32 * k]);
            float2 cf = c2[lane + 32 * k];
            float2 o;
            o.x = (1.0f + kf.x) * rv * cf.x;
            o.y = (1.0f + kf.y) * rv * cf.y;
            *(float2*)&orow[2 * (lane + 32 * k)] = o;
        }
    }
}

// ---------------- launcher -------------------------------------------------------
extern "C" void kernel_launch(void* const* d_in, const int* in_sizes, int n_in,
                              void* d_out, int out_size)
{
    const float*         ein  = (const float*)d_in[0];
    const unsigned char* mraw = (const unsigned char*)d_in[1];   // bool OR int32, sniffed
    const float*         eout = (const float*)d_in[2];
    const float*         pad  = (const float*)d_in[3];
    const float*         pos  = (const float*)d_in[4];
    const float*         Win  = (const float*)d_in[5];
    const float*         bin  = (const float*)d_in[6];
    const float*         Wout = (const float*)d_in[7];
    const float*         bout = (const float*)d_in[8];
    float* out = (float*)d_out;

    cudaFuncSetAttribute(k_ab, cudaFuncAttributeMaxDynamicSharedMemorySize,
                         (int)sizeof(AbSmem));
    k_ab<<<(Bc * Nc) / CN, 512, sizeof(AbSmem)>>>(ein, mraw, eout, pad, pos,
                                                  Win, bin, Wout, bout);

    dim3 g2(Nc / 32, Nc / 32, Bc);
    k_cost<<<g2, 256>>>();

    // 16-CTA cluster: non-portable size, runtime cluster dims
    cudaFuncSetAttribute(k_sinkhorn, cudaFuncAttributeNonPortableClusterSizeAllowed, 1);
    cudaFuncSetAttribute(k_sinkhorn, cudaFuncAttributeMaxDynamicSharedMemorySize,
                         (int)sizeof(SmemLayout));
    cudaLaunchConfig_t cfg = {};
    cfg.gridDim  = dim3(Bc * CSZ, 1, 1);
    cfg.blockDim = dim3(TPB, 1, 1);
    cfg.dynamicSmemBytes = sizeof(SmemLayout);
    cudaLaunchAttribute attrs[1];
    attrs[0].id = cudaLaunchAttributeClusterDimension;
    attrs[0].val.clusterDim = {CSZ, 1, 1};
    cfg.attrs = attrs;
    cfg.numAttrs = 1;
    cudaLaunchKernelEx(&cfg, k_sinkhorn, out);
}

// round 13
// speedup vs baseline: 1.3673x; 1.3673x over previous
#include <cuda_runtime.h>
#include <cuda_fp16.h>
#include <cooperative_groups.h>

namespace cg = cooperative_groups;

// Problem constants
constexpr int Bc = 8;
constexpr int Nc = 512;
constexpr int Dc = 256;
constexpr int Mc = 32;
constexpr float EPS = 1e-4f;
constexpr int NIT = 3;       // kappa ~ 0.026 -> residual after 3 iters ~1e-6 << fp16 floor

// Sinkhorn kernel config (reverted to CSZ=8 — R12's CSZ=16 regressed +11.8us)
constexpr int CSZ = 8;           // cluster size (CTAs per batch)
constexpr int RPC = Nc / CSZ;    // rows per CTA = 64
constexpr int TPB = 512;         // threads per block (16 warps)

// k_ab config: 16 nodes per block, 256 blocks
constexpr int CN  = 16;          // nodes per block

// ---------------- scratch (device globals; no allocation allowed) ----------------
__device__ float  g_a[Bc * Nc * Mc];
__device__ float  g_b[Bc * Nc * Mc];
__device__ __half g_Ch [(size_t)Bc * Nc * Nc];        // 4 MB fp16 raw cost, row-major
__device__ __half g_CTh[(size_t)Bc * Nc * Nc];        // 4 MB fp16 raw cost, transposed
__device__ float  g_sumC[Bc];

extern __shared__ char dynsmem[];

// ---------------- K1: projections; warp-halves split a/b; 16 nodes/block ---------
struct AbSmem {
    float s_in [CN][Dc];       // 16 KB
    float s_out[CN][Dc];       // 16 KB
    float red_a[CN][8][Mc];    // 16 KB
    float red_b[CN][8][Mc];    // 16 KB
    int   s_wb[16];
};

__global__ void __launch_bounds__(512, 2)
k_ab(const float* __restrict__ ein, const unsigned char* __restrict__ mraw,
     const float* __restrict__ eout, const float* __restrict__ pad,
     const float* __restrict__ pos, const float* __restrict__ Win,
     const float* __restrict__ bin, const float* __restrict__ Wout,
     const float* __restrict__ bout)
{
    AbSmem* sm = (AbSmem*)dynsmem;

    int tid  = threadIdx.x;          // 512
    int lane = tid & 31;
    int wid  = tid >> 5;             // 16 warps
    bool isA = wid < 8;
    int seg  = wid & 7;              // 8 segments of 32 d's per projection
    int nb0  = blockIdx.x * CN;      // first node (b*N flat index)

    if (blockIdx.x < Bc && tid == 0) g_sumC[blockIdx.x] = 0.f;

    // ---- issue ALL global loads immediately ----
    unsigned sv = ((const unsigned*)mraw)[tid & 255];      // sniff word (first 1KB)

    float4 i4[2], pd4[2];
    unsigned char mb[2]; int mw[2]; int nds[2], d4s[2];
#pragma unroll
    for (int k = 0; k < 2; k++) {
        int f  = tid + k * 512;
        int nd = f >> 6;                 // node in chunk (0..15)
        int d4 = (f & 63) * 4;           // dim offset
        int bn = nb0 + nd;
        int n  = bn & (Nc - 1);
        nds[k] = nd; d4s[k] = d4;
        float4 a4 = *(const float4*)&eout[(size_t)bn * Dc + d4];
        float4 p4 = *(const float4*)&pos[(size_t)n * Dc + d4];
        a4.x += p4.x; a4.y += p4.y; a4.z += p4.z; a4.w += p4.w;
        *(float4*)&sm->s_out[nd][d4] = a4;            // mask-independent: store now
        i4[k]  = *(const float4*)&ein[(size_t)bn * Dc + d4];
        pd4[k] = *(const float4*)&pad[d4];
        mb[k]  = mraw[bn];                            // bool-layout interpretation
        mw[k]  = ((const int*)mraw)[bn];              // int32-layout interpretation
    }

    float W[32];
    {
        const float* Wsel = isA ? Wout : Win;
        int d0 = seg * 32;
#pragma unroll
        for (int dd = 0; dd < 32; dd++) W[dd] = Wsel[(d0 + dd) * Mc + lane];
    }

    {
        int any = __any_sync(0xffffffffu, (sv & 0xFFFFFF00u) != 0);
        if (lane == 0) sm->s_wb[wid] = any;
    }
    __syncthreads();
    bool isBool = (sm->s_wb[0] | sm->s_wb[1] | sm->s_wb[2]  | sm->s_wb[3]  |
                   sm->s_wb[4] | sm->s_wb[5] | sm->s_wb[6]  | sm->s_wb[7]  |
                   sm->s_wb[8] | sm->s_wb[9] | sm->s_wb[10] | sm->s_wb[11] |
                   sm->s_wb[12]| sm->s_wb[13]| sm->s_wb[14] | sm->s_wb[15]) != 0;

#pragma unroll
    for (int k = 0; k < 2; k++) {
        bool pm = isBool ? (mb[k] != 0) : (mw[k] != 0);
        *(float4*)&sm->s_in[nds[k]][d4s[k]] = pm ? pd4[k] : i4[k];
    }
    __syncthreads();

    {
        const float (*X)[Dc] = isA ? sm->s_out : sm->s_in;
        float (*R)[8][Mc]    = isA ? sm->red_a : sm->red_b;
        int d0 = seg * 32;
#pragma unroll
        for (int nd2 = 0; nd2 < CN; nd2++) {
            float pa = 0.f;
#pragma unroll
            for (int q = 0; q < 8; q++) {
                float4 x = *(const float4*)&X[nd2][d0 + q * 4];
                pa += x.x * W[q*4+0] + x.y * W[q*4+1] + x.z * W[q*4+2] + x.w * W[q*4+3];
            }
            R[nd2][seg][lane] = pa;
        }
    }
    __syncthreads();

    {
        int nd3 = tid >> 5;              // node (0..15)
        int m3  = tid & 31;              // m
        float sa = bout[m3], sb = bin[m3];
#pragma unroll
        for (int sgi = 0; sgi < 8; sgi++) {
            sa += sm->red_a[nd3][sgi][m3];
            sb += sm->red_b[nd3][sgi][m3];
        }
        size_t o = (size_t)(nb0 + nd3) * Mc + m3;
        g_a[o] = sa;
        g_b[o] = sb;
    }
}

// ---------------- K2: C[b,i,j] = sum_m |a[i,m]-b[j,m]| -> fp16 C and C^T + sum ---
__global__ void k_cost()
{
    int b  = blockIdx.z;
    int i0 = blockIdx.y * 32;
    int j0 = blockIdx.x * 32;
    __shared__ float a_s[32][36], b_s[32][36];   // rows 144B: 16B-aligned, odd uint4 stride
    __shared__ float t_s[32][33];
    __shared__ float wsum[8];
    int tid = threadIdx.x;            // 256
    for (int idx = tid; idx < 1024; idx += 256) {
        int r = idx >> 5, m = idx & 31;
        a_s[r][m] = g_a[((size_t)b * Nc + i0 + r) * Mc + m];
        b_s[r][m] = g_b[((size_t)b * Nc + j0 + r) * Mc + m];
    }
    __syncthreads();

    int j = tid & 31, ig = tid >> 5;
    float acc0 = 0.f, acc1 = 0.f, acc2 = 0.f, acc3 = 0.f;
#pragma unroll
    for (int mq = 0; mq < 8; mq++) {
        float4 bv = *(const float4*)&b_s[j][mq * 4];
        float4 x0 = *(const float4*)&a_s[ig     ][mq * 4];
        float4 x1 = *(const float4*)&a_s[ig +  8][mq * 4];
        float4 x2 = *(const float4*)&a_s[ig + 16][mq * 4];
        float4 x3 = *(const float4*)&a_s[ig + 24][mq * 4];
        acc0 += fabsf(x0.x - bv.x) + fabsf(x0.y - bv.y) + fabsf(x0.z - bv.z) + fabsf(x0.w - bv.w);
        acc1 += fabsf(x1.x - bv.x) + fabsf(x1.y - bv.y) + fabsf(x1.z - bv.z) + fabsf(x1.w - bv.w);
        acc2 += fabsf(x2.x - bv.x) + fabsf(x2.y - bv.y) + fabsf(x2.z - bv.z) + fabsf(x2.w - bv.w);
        acc3 += fabsf(x3.x - bv.x) + fabsf(x3.y - bv.y) + fabsf(x3.z - bv.z) + fabsf(x3.w - bv.w);
    }
    t_s[ig     ][j] = acc0;
    t_s[ig +  8][j] = acc1;
    t_s[ig + 16][j] = acc2;
    t_s[ig + 24][j] = acc3;

    float lsum = (acc0 + acc1) + (acc2 + acc3);
    lsum += __shfl_xor_sync(0xffffffffu, lsum, 16);
    lsum += __shfl_xor_sync(0xffffffffu, lsum, 8);
    lsum += __shfl_xor_sync(0xffffffffu, lsum, 4);
    lsum += __shfl_xor_sync(0xffffffffu, lsum, 2);
    lsum += __shfl_xor_sync(0xffffffffu, lsum, 1);
    if ((tid & 31) == 0) wsum[tid >> 5] = lsum;
    __syncthreads();
    if (tid == 0) {
        float s = 0.f;
#pragma unroll
        for (int w = 0; w < 8; w++) s += wsum[w];
        atomicAdd(&g_sumC[b], s);
    }

    int r  = tid >> 3;
    int c0 = (tid & 7) * 4;
    {
        __half2 h01 = __floats2half2_rn(t_s[r][c0],     t_s[r][c0 + 1]);
        __half2 h23 = __floats2half2_rn(t_s[r][c0 + 2], t_s[r][c0 + 3]);
        size_t cb = ((size_t)b * Nc + i0 + r) * Nc + j0 + c0;
        *(__half2*)&g_Ch[cb]     = h01;
        *(__half2*)&g_Ch[cb + 2] = h23;
    }
    {
        __half2 h01 = __floats2half2_rn(t_s[c0][r],     t_s[c0 + 1][r]);
        __half2 h23 = __floats2half2_rn(t_s[c0 + 2][r], t_s[c0 + 3][r]);
        size_t tb = ((size_t)b * Nc + j0 + r) * Nc + i0 + c0;
        *(__half2*)&g_CTh[tb]     = h01;
        *(__half2*)&g_CTh[tb + 2] = h23;
    }
}

// ---------------- K3: Sinkhorn, 8-CTA cluster, K + K^T resident in SMEM ----------
struct SmemLayout {
    __half Ks [RPC * Nc];    // 64 KB : this CTA's 64 rows of (K-1)
    __half KsT[RPC * Nc];    // 64 KB : this CTA's 64 columns of (K-1) (contiguous after Ks)
    float  c_s[Nc];
    float  r_s[Nc];
    float  r_own[RPC];
    float  c_own[RPC];
    float  rsum[CSZ];
    float  csum[CSZ];
};

__device__ __forceinline__ float warp_sum(float v) {
    v += __shfl_xor_sync(0xffffffffu, v, 16);
    v += __shfl_xor_sync(0xffffffffu, v, 8);
    v += __shfl_xor_sync(0xffffffffu, v, 4);
    v += __shfl_xor_sync(0xffffffffu, v, 2);
    v += __shfl_xor_sync(0xffffffffu, v, 1);
    return v;
}

// 4-row half2 matvec: out[row] = inv_n / (S + sum_j slab[row][j]*vec[j])
__device__ __forceinline__ void matvec4(const __half2* __restrict__ slab2,
                                        const float* __restrict__ vec,
                                        float* __restrict__ outv,
                                        float S, float inv_n, int w, int lane)
{
    float2 vf[8];
    const float2* v2 = (const float2*)vec;
#pragma unroll
    for (int k = 0; k < 8; k++) vf[k] = v2[lane + 32 * k];
#pragma unroll
    for (int rr = 0; rr < 4; rr++) {
        int row = w * 4 + rr;
        const __half2* kr = slab2 + row * (Nc / 2);
        float y = 0.f;
#pragma unroll
        for (int k = 0; k < 8; k++) {
            float2 kf = __half22float2(kr[lane + 32 * k]);
            y += kf.x * vf[k].x + kf.y * vf[k].y;
        }
        y = warp_sum(y);
        if (lane == 0) outv[row] = inv_n / (S + y);
    }
}

__global__ void __cluster_dims__(CSZ, 1, 1) __launch_bounds__(TPB, 1)
k_sinkhorn(float* __restrict__ out)
{
    cg::cluster_group cluster = cg::this_cluster();
    unsigned rank = cluster.block_rank();
    int b = blockIdx.x / CSZ;
    SmemLayout* s = (SmemLayout*)dynsmem;

    int tid  = threadIdx.x;
    int lane = tid & 31;
    int w    = tid >> 5;          // 16 warps
    int jl   = tid & 63;          // column-within-chunk for exchange (RPC=64)
    int dstR = tid >> 6;          // destination rank for exchange (0..7)

    // Load raw-C row slab + column slab (64 KB each), linear int4 copies
    {
        const int4* srcR_ = (const int4*)(g_Ch  + ((size_t)b * Nc + rank * RPC) * Nc);
        const int4* srcT  = (const int4*)(g_CTh + ((size_t)b * Nc + rank * RPC) * Nc);
        int4* dR = (int4*)s->Ks;
        int4* dT = (int4*)s->KsT;
#pragma unroll
        for (int t = tid; t < RPC * Nc * 2 / 16; t += TPB) { dR[t] = srcR_[t]; dT[t] = srcT[t]; }
    }
    s->c_s[tid] = 1.0f;                         // c0 = 1
    if (tid < CSZ) s->csum[tid] = (float)RPC;   // each rank's c-chunk sums to 64
    __syncthreads();

    // In-place convert: Kp = expm1(-C*inv), half2 Taylor (covers Ks+KsT contiguously)
    {
        float inv = 1.f / (EPS * g_sumC[b]);
        __half2 ninv2 = __float2half2_rn(-inv);
        const __half2 c4 = __float2half2_rn(1.f / 24.f);
        const __half2 c3 = __float2half2_rn(1.f / 6.f);
        const __half2 c2 = __float2half2_rn(0.5f);
        const __half2 c1 = __float2half2_rn(1.0f);
        __half2* p = (__half2*)s->Ks;    // RPC*Nc half2 = both 64KB slabs
#pragma unroll
        for (int t = tid; t < RPC * Nc; t += TPB) {
            __half2 x = __hmul2(p[t], ninv2);
            __half2 q = __hfma2(x, c4, c3);
            q = __hfma2(x, q, c2);
            q = __hfma2(x, q, c1);
            p[t] = __hmul2(x, q);
        }
    }
    __syncthreads();

    const float inv_n = 1.0f / (float)Nc;
    const __half2* Ks2  = (const __half2*)s->Ks;
    const __half2* KsT2 = (const __half2*)s->KsT;

    float* remote_r = (float*)cluster.map_shared_rank(s->r_s, dstR) + rank * RPC + jl;
    float* remote_c = (float*)cluster.map_shared_rank(s->c_s, dstR) + rank * RPC + jl;

    for (int it = 0; it < NIT; it++) {
        // ---- Phase A: r_own = inv_n / (S_c + Kp_rows . c) ----
        float S_c = ((s->csum[0] + s->csum[1]) + (s->csum[2] + s->csum[3]))
                  + ((s->csum[4] + s->csum[5]) + (s->csum[6] + s->csum[7]));
        matvec4(Ks2, s->c_s, s->r_own, S_c, inv_n, w, lane);
        __syncthreads();

        // chunk partial sum -> all ranks' rsum; broadcast r_own -> all ranks' r_s
        if (w == 0) {
            float v = warp_sum(s->r_own[lane] + s->r_own[lane + 32]);
            if (lane < CSZ)
                ((float*)cluster.map_shared_rank(s->rsum, lane))[rank] = v;
        }
        *remote_r = s->r_own[jl];
        cluster.sync();

        // ---- Phase B: c_own = inv_n / (S_r + Kp_cols . r) ----
        float S_r = ((s->rsum[0] + s->rsum[1]) + (s->rsum[2] + s->rsum[3]))
                  + ((s->rsum[4] + s->rsum[5]) + (s->rsum[6] + s->rsum[7]));
        matvec4(KsT2, s->r_s, s->c_own, S_r, inv_n, w, lane);
        __syncthreads();

        if (w == 0) {
            float v = warp_sum(s->c_own[lane] + s->c_own[lane + 32]);
            if (lane < CSZ)
                ((float*)cluster.map_shared_rank(s->csum, lane))[rank] = v;
        }
        *remote_c = s->c_own[jl];
        cluster.sync();
    }

    // ---- epilogue: P[b,i,j] = (1 + Kp[i,j]) * r_i * c_j ----
    float* Ob = out + ((size_t)b * Nc + rank * RPC) * Nc;
#pragma unroll
    for (int rr = 0; rr < 4; rr++) {
        int row = w * 4 + rr;
        float rv = s->r_own[row];
        float* orow = Ob + (size_t)row * Nc;
        const __half2* kr = (const __half2*)s->Ks + row * (Nc / 2);
        const float2* c2 = (const float2*)s->c_s;
#pragma unroll
        for (int k = 0; k < 8; k++) {
            float2 kf = __half22float2(kr[lane + 32 * k]);
            float2 cf = c2[lane + 32 * k];
            float2 o;
            o.x = (1.0f + kf.x) * rv * cf.x;
            o.y = (1.0f + kf.y) * rv * cf.y;
            *(float2*)&orow[2 * (lane + 32 * k)] = o;
        }
    }
}

// ---------------- launcher -------------------------------------------------------
extern "C" void kernel_launch(void* const* d_in, const int* in_sizes, int n_in,
                              void* d_out, int out_size)
{
    const float*         ein  = (const float*)d_in[0];
    const unsigned char* mraw = (const unsigned char*)d_in[1];   // bool OR int32, sniffed
    const float*         eout = (const float*)d_in[2];
    const float*         pad  = (const float*)d_in[3];
    const float*         pos  = (const float*)d_in[4];
    const float*         Win  = (const float*)d_in[5];
    const float*         bin  = (const float*)d_in[6];
    const float*         Wout = (const float*)d_in[7];
    const float*         bout = (const float*)d_in[8];
    float* out = (float*)d_out;

    cudaFuncSetAttribute(k_ab, cudaFuncAttributeMaxDynamicSharedMemorySize,
                         (int)sizeof(AbSmem));
    k_ab<<<(Bc * Nc) / CN, 512, sizeof(AbSmem)>>>(ein, mraw, eout, pad, pos,
                                                  Win, bin, Wout, bout);

    dim3 g2(Nc / 32, Nc / 32, Bc);
    k_cost<<<g2, 256>>>();

    cudaFuncSetAttribute(k_sinkhorn, cudaFuncAttributeMaxDynamicSharedMemorySize,
                         (int)sizeof(SmemLayout));
    k_sinkhorn<<<Bc * CSZ, TPB, sizeof(SmemLayout)>>>(out);
}

// round 14
// speedup vs baseline: 1.4966x; 1.0946x over previous
#include <cuda_runtime.h>
#include <cuda_fp16.h>
#include <cooperative_groups.h>

namespace cg = cooperative_groups;

// Problem constants
constexpr int Bc = 8;
constexpr int Nc = 512;
constexpr int Dc = 256;
constexpr int Mc = 32;
constexpr float EPS = 1e-4f;
constexpr int NIT = 2;       // kappa ~ 0.015, d0 ~ 0.01 -> residual ~2e-6 << fp16 floor

// Sinkhorn kernel config
constexpr int CSZ = 8;           // cluster size (CTAs per batch)
constexpr int RPC = Nc / CSZ;    // rows per CTA = 64
constexpr int TPB = 512;         // threads per block (16 warps)

// k_ab config: 16 nodes per block, 256 blocks
constexpr int CN  = 16;          // nodes per block

// PDL helpers (no-ops when kernel not launched as programmatic dependent)
__device__ __forceinline__ void pdl_wait()    { asm volatile("griddepcontrol.wait;" ::: "memory"); }
__device__ __forceinline__ void pdl_trigger() { asm volatile("griddepcontrol.launch_dependents;" ::: "memory"); }

// ---------------- scratch (device globals; no allocation allowed) ----------------
__device__ float  g_a[Bc * Nc * Mc];
__device__ float  g_b[Bc * Nc * Mc];
__device__ __half g_Ch [(size_t)Bc * Nc * Nc];        // 4 MB fp16 raw cost, row-major
__device__ __half g_CTh[(size_t)Bc * Nc * Nc];        // 4 MB fp16 raw cost, transposed
__device__ float  g_sumC[Bc];

extern __shared__ char dynsmem[];

// ---------------- K1: projections; warp-halves split a/b; 16 nodes/block ---------
struct AbSmem {
    float s_in [CN][Dc];       // 16 KB
    float s_out[CN][Dc];       // 16 KB
    float red_a[CN][8][Mc];    // 16 KB
    float red_b[CN][8][Mc];    // 16 KB
    int   s_wb[16];
};

__global__ void __launch_bounds__(512, 2)
k_ab(const float* __restrict__ ein, const unsigned char* __restrict__ mraw,
     const float* __restrict__ eout, const float* __restrict__ pad,
     const float* __restrict__ pos, const float* __restrict__ Win,
     const float* __restrict__ bin, const float* __restrict__ Wout,
     const float* __restrict__ bout)
{
    AbSmem* sm = (AbSmem*)dynsmem;

    int tid  = threadIdx.x;          // 512
    int lane = tid & 31;
    int wid  = tid >> 5;             // 16 warps
    bool isA = wid < 8;
    int seg  = wid & 7;              // 8 segments of 32 d's per projection
    int nb0  = blockIdx.x * CN;      // first node (b*N flat index)

    if (blockIdx.x < Bc && tid == 0) g_sumC[blockIdx.x] = 0.f;

    // ---- issue ALL global loads immediately ----
    unsigned sv = ((const unsigned*)mraw)[tid & 255];      // sniff word (first 1KB)

    float4 i4[2], pd4[2];
    unsigned char mb[2]; int mw[2]; int nds[2], d4s[2];
#pragma unroll
    for (int k = 0; k < 2; k++) {
        int f  = tid + k * 512;
        int nd = f >> 6;                 // node in chunk (0..15)
        int d4 = (f & 63) * 4;           // dim offset
        int bn = nb0 + nd;
        int n  = bn & (Nc - 1);
        nds[k] = nd; d4s[k] = d4;
        float4 a4 = *(const float4*)&eout[(size_t)bn * Dc + d4];
        float4 p4 = *(const float4*)&pos[(size_t)n * Dc + d4];
        a4.x += p4.x; a4.y += p4.y; a4.z += p4.z; a4.w += p4.w;
        *(float4*)&sm->s_out[nd][d4] = a4;            // mask-independent: store now
        i4[k]  = *(const float4*)&ein[(size_t)bn * Dc + d4];
        pd4[k] = *(const float4*)&pad[d4];
        mb[k]  = mraw[bn];                            // bool-layout interpretation
        mw[k]  = ((const int*)mraw)[bn];              // int32-layout interpretation
    }

    float W[32];
    {
        const float* Wsel = isA ? Wout : Win;
        int d0 = seg * 32;
#pragma unroll
        for (int dd = 0; dd < 32; dd++) W[dd] = Wsel[(d0 + dd) * Mc + lane];
    }

    {
        int any = __any_sync(0xffffffffu, (sv & 0xFFFFFF00u) != 0);
        if (lane == 0) sm->s_wb[wid] = any;
    }
    __syncthreads();
    bool isBool = (sm->s_wb[0] | sm->s_wb[1] | sm->s_wb[2]  | sm->s_wb[3]  |
                   sm->s_wb[4] | sm->s_wb[5] | sm->s_wb[6]  | sm->s_wb[7]  |
                   sm->s_wb[8] | sm->s_wb[9] | sm->s_wb[10] | sm->s_wb[11] |
                   sm->s_wb[12]| sm->s_wb[13]| sm->s_wb[14] | sm->s_wb[15]) != 0;

#pragma unroll
    for (int k = 0; k < 2; k++) {
        bool pm = isBool ? (mb[k] != 0) : (mw[k] != 0);
        *(float4*)&sm->s_in[nds[k]][d4s[k]] = pm ? pd4[k] : i4[k];
    }
    __syncthreads();

    {
        const float (*X)[Dc] = isA ? sm->s_out : sm->s_in;
        float (*R)[8][Mc]    = isA ? sm->red_a : sm->red_b;
        int d0 = seg * 32;
#pragma unroll
        for (int nd2 = 0; nd2 < CN; nd2++) {
            float pa = 0.f;
#pragma unroll
            for (int q = 0; q < 8; q++) {
                float4 x = *(const float4*)&X[nd2][d0 + q * 4];
                pa += x.x * W[q*4+0] + x.y * W[q*4+1] + x.z * W[q*4+2] + x.w * W[q*4+3];
            }
            R[nd2][seg][lane] = pa;
        }
    }
    __syncthreads();

    {
        int nd3 = tid >> 5;              // node (0..15)
        int m3  = tid & 31;              // m
        float sa = bout[m3], sb = bin[m3];
#pragma unroll
        for (int sgi = 0; sgi < 8; sgi++) {
            sa += sm->red_a[nd3][sgi][m3];
            sb += sm->red_b[nd3][sgi][m3];
        }
        size_t o = (size_t)(nb0 + nd3) * Mc + m3;
        g_a[o] = sa;
        g_b[o] = sb;
    }
    pdl_trigger();   // after ALL global writes of this CTA
}

// ---------------- K2: C[b,i,j] = sum_m |a[i,m]-b[j,m]| -> fp16 C and C^T + sum ---
__global__ void k_cost()
{
    int b  = blockIdx.z;
    int i0 = blockIdx.y * 32;
    int j0 = blockIdx.x * 32;
    __shared__ float a_s[32][36], b_s[32][36];   // rows 144B: 16B-aligned, odd uint4 stride
    __shared__ float t_s[32][33];
    __shared__ float wsum[8];
    int tid = threadIdx.x;            // 256

    pdl_wait();   // g_a/g_b produced by k_ab

    for (int idx = tid; idx < 1024; idx += 256) {
        int r = idx >> 5, m = idx & 31;
        a_s[r][m] = g_a[((size_t)b * Nc + i0 + r) * Mc + m];
        b_s[r][m] = g_b[((size_t)b * Nc + j0 + r) * Mc + m];
    }
    __syncthreads();

    int j = tid & 31, ig = tid >> 5;
    float acc0 = 0.f, acc1 = 0.f, acc2 = 0.f, acc3 = 0.f;
#pragma unroll
    for (int mq = 0; mq < 8; mq++) {
        float4 bv = *(const float4*)&b_s[j][mq * 4];
        float4 x0 = *(const float4*)&a_s[ig     ][mq * 4];
        float4 x1 = *(const float4*)&a_s[ig +  8][mq * 4];
        float4 x2 = *(const float4*)&a_s[ig + 16][mq * 4];
        float4 x3 = *(const float4*)&a_s[ig + 24][mq * 4];
        acc0 += fabsf(x0.x - bv.x) + fabsf(x0.y - bv.y) + fabsf(x0.z - bv.z) + fabsf(x0.w - bv.w);
        acc1 += fabsf(x1.x - bv.x) + fabsf(x1.y - bv.y) + fabsf(x1.z - bv.z) + fabsf(x1.w - bv.w);
        acc2 += fabsf(x2.x - bv.x) + fabsf(x2.y - bv.y) + fabsf(x2.z - bv.z) + fabsf(x2.w - bv.w);
        acc3 += fabsf(x3.x - bv.x) + fabsf(x3.y - bv.y) + fabsf(x3.z - bv.z) + fabsf(x3.w - bv.w);
    }
    t_s[ig     ][j] = acc0;
    t_s[ig +  8][j] = acc1;
    t_s[ig + 16][j] = acc2;
    t_s[ig + 24][j] = acc3;

    float lsum = (acc0 + acc1) + (acc2 + acc3);
    lsum += __shfl_xor_sync(0xffffffffu, lsum, 16);
    lsum += __shfl_xor_sync(0xffffffffu, lsum, 8);
    lsum += __shfl_xor_sync(0xffffffffu, lsum, 4);
    lsum += __shfl_xor_sync(0xffffffffu, lsum, 2);
    lsum += __shfl_xor_sync(0xffffffffu, lsum, 1);
    if ((tid & 31) == 0) wsum[tid >> 5] = lsum;
    __syncthreads();
    if (tid == 0) {
        float s = 0.f;
#pragma unroll
        for (int w = 0; w < 8; w++) s += wsum[w];
        atomicAdd(&g_sumC[b], s);
    }

    int r  = tid >> 3;
    int c0 = (tid & 7) * 4;
    {
        __half2 h01 = __floats2half2_rn(t_s[r][c0],     t_s[r][c0 + 1]);
        __half2 h23 = __floats2half2_rn(t_s[r][c0 + 2], t_s[r][c0 + 3]);
        size_t cb = ((size_t)b * Nc + i0 + r) * Nc + j0 + c0;
        *(__half2*)&g_Ch[cb]     = h01;
        *(__half2*)&g_Ch[cb + 2] = h23;
    }
    {
        __half2 h01 = __floats2half2_rn(t_s[c0][r],     t_s[c0 + 1][r]);
        __half2 h23 = __floats2half2_rn(t_s[c0 + 2][r], t_s[c0 + 3][r]);
        size_t tb = ((size_t)b * Nc + j0 + r) * Nc + i0 + c0;
        *(__half2*)&g_CTh[tb]     = h01;
        *(__half2*)&g_CTh[tb + 2] = h23;
    }
    pdl_trigger();   // after ALL global writes of this CTA
}

// ---------------- K3: Sinkhorn, 8-CTA cluster, K + K^T resident in SMEM ----------
struct SmemLayout {
    __half Ks [RPC * Nc];    // 64 KB : this CTA's 64 rows of (K-1)
    __half KsT[RPC * Nc];    // 64 KB : this CTA's 64 columns of (K-1) (contiguous after Ks)
    float  c_s[Nc];
    float  r_s[Nc];
    float  r_own[RPC];
    float  c_own[RPC];
    float  rsum[CSZ];
    float  csum[CSZ];
};

__device__ __forceinline__ float warp_sum(float v) {
    v += __shfl_xor_sync(0xffffffffu, v, 16);
    v += __shfl_xor_sync(0xffffffffu, v, 8);
    v += __shfl_xor_sync(0xffffffffu, v, 4);
    v += __shfl_xor_sync(0xffffffffu, v, 2);
    v += __shfl_xor_sync(0xffffffffu, v, 1);
    return v;
}

// 4-row half2 matvec: out[row] = inv_n / (S + sum_j slab[row][j]*vec[j])
__device__ __forceinline__ void matvec4(const __half2* __restrict__ slab2,
                                        const float* __restrict__ vec,
                                        float* __restrict__ outv,
                                        float S, float inv_n, int w, int lane)
{
    float2 vf[8];
    const float2* v2 = (const float2*)vec;
#pragma unroll
    for (int k = 0; k < 8; k++) vf[k] = v2[lane + 32 * k];
#pragma unroll
    for (int rr = 0; rr < 4; rr++) {
        int row = w * 4 + rr;
        const __half2* kr = slab2 + row * (Nc / 2);
        float y = 0.f;
#pragma unroll
        for (int k = 0; k < 8; k++) {
            float2 kf = __half22float2(kr[lane + 32 * k]);
            y += kf.x * vf[k].x + kf.y * vf[k].y;
        }
        y = warp_sum(y);
        if (lane == 0) outv[row] = inv_n / (S + y);
    }
}

__global__ void __cluster_dims__(CSZ, 1, 1) __launch_bounds__(TPB, 1)
k_sinkhorn(float* __restrict__ out)
{
    cg::cluster_group cluster = cg::this_cluster();
    unsigned rank = cluster.block_rank();
    int b = blockIdx.x / CSZ;
    SmemLayout* s = (SmemLayout*)dynsmem;

    int tid  = threadIdx.x;
    int lane = tid & 31;
    int w    = tid >> 5;          // 16 warps
    int jl   = tid & 63;          // column-within-chunk for exchange (RPC=64)
    int dstR = tid >> 6;          // destination rank for exchange (0..7)

    // independent prologue before the PDL wait
    s->c_s[tid] = 1.0f;                         // c0 = 1
    if (tid < CSZ) s->csum[tid] = (float)RPC;   // each rank's c-chunk sums to 64

    pdl_wait();   // g_Ch/g_CTh/g_sumC produced by k_cost

    // Load raw-C row slab + column slab (64 KB each), linear int4 copies
    {
        const int4* srcR_ = (const int4*)(g_Ch  + ((size_t)b * Nc + rank * RPC) * Nc);
        const int4* srcT  = (const int4*)(g_CTh + ((size_t)b * Nc + rank * RPC) * Nc);
        int4* dR = (int4*)s->Ks;
        int4* dT = (int4*)s->KsT;
#pragma unroll
        for (int t = tid; t < RPC * Nc * 2 / 16; t += TPB) { dR[t] = srcR_[t]; dT[t] = srcT[t]; }
    }
    __syncthreads();

    // In-place convert: Kp = expm1(-C*inv), half2 Taylor (covers Ks+KsT contiguously)
    {
        float inv = 1.f / (EPS * g_sumC[b]);
        __half2 ninv2 = __float2half2_rn(-inv);
        const __half2 c4 = __float2half2_rn(1.f / 24.f);
        const __half2 c3 = __float2half2_rn(1.f / 6.f);
        const __half2 c2 = __float2half2_rn(0.5f);
        const __half2 c1 = __float2half2_rn(1.0f);
        __half2* p = (__half2*)s->Ks;    // RPC*Nc half2 = both 64KB slabs
#pragma unroll
        for (int t = tid; t < RPC * Nc; t += TPB) {
            __half2 x = __hmul2(p[t], ninv2);
            __half2 q = __hfma2(x, c4, c3);
            q = __hfma2(x, q, c2);
            q = __hfma2(x, q, c1);
            p[t] = __hmul2(x, q);
        }
    }
    __syncthreads();

    const float inv_n = 1.0f / (float)Nc;
    const __half2* Ks2  = (const __half2*)s->Ks;
    const __half2* KsT2 = (const __half2*)s->KsT;

    float* remote_r = (float*)cluster.map_shared_rank(s->r_s, dstR) + rank * RPC + jl;
    float* remote_c = (float*)cluster.map_shared_rank(s->c_s, dstR) + rank * RPC + jl;

    for (int it = 0; it < NIT; it++) {
        // ---- Phase A: r_own = inv_n / (S_c + Kp_rows . c) ----
        float S_c = ((s->csum[0] + s->csum[1]) + (s->csum[2] + s->csum[3]))
                  + ((s->csum[4] + s->csum[5]) + (s->csum[6] + s->csum[7]));
        matvec4(Ks2, s->c_s, s->r_own, S_c, inv_n, w, lane);
        __syncthreads();

        // chunk partial sum -> all ranks' rsum; broadcast r_own -> all ranks' r_s
        if (w == 0) {
            float v = warp_sum(s->r_own[lane] + s->r_own[lane + 32]);
            if (lane < CSZ)
                ((float*)cluster.map_shared_rank(s->rsum, lane))[rank] = v;
        }
        *remote_r = s->r_own[jl];
        cluster.sync();

        // ---- Phase B: c_own = inv_n / (S_r + Kp_cols . r) ----
        float S_r = ((s->rsum[0] + s->rsum[1]) + (s->rsum[2] + s->rsum[3]))
                  + ((s->rsum[4] + s->rsum[5]) + (s->rsum[6] + s->rsum[7]));
        matvec4(KsT2, s->r_s, s->c_own, S_r, inv_n, w, lane);
        __syncthreads();

        if (w == 0) {
            float v = warp_sum(s->c_own[lane] + s->c_own[lane + 32]);
            if (lane < CSZ)
                ((float*)cluster.map_shared_rank(s->csum, lane))[rank] = v;
        }
        *remote_c = s->c_own[jl];
        cluster.sync();
    }

    // ---- epilogue: P[b,i,j] = (1 + Kp[i,j]) * r_i * c_j ----
    float* Ob = out + ((size_t)b * Nc + rank * RPC) * Nc;
#pragma unroll
    for (int rr = 0; rr < 4; rr++) {
        int row = w * 4 + rr;
        float rv = s->r_own[row];
        float* orow = Ob + (size_t)row * Nc;
        const __half2* kr = (const __half2*)s->Ks + row * (Nc / 2);
        const float2* c2 = (const float2*)s->c_s;
#pragma unroll
        for (int k = 0; k < 8; k++) {
            float2 kf = __half22float2(kr[lane + 32 * k]);
            float2 cf = c2[lane + 32 * k];
            float2 o;
            o.x = (1.0f + kf.x) * rv * cf.x;
            o.y = (1.0f + kf.y) * rv * cf.y;
            *(float2*)&orow[2 * (lane + 32 * k)] = o;
        }
    }
}

// ---------------- launcher -------------------------------------------------------
extern "C" void kernel_launch(void* const* d_in, const int* in_sizes, int n_in,
                              void* d_out, int out_size)
{
    const float*         ein  = (const float*)d_in[0];
    const unsigned char* mraw = (const unsigned char*)d_in[1];   // bool OR int32, sniffed
    const float*         eout = (const float*)d_in[2];
    const float*         pad  = (const float*)d_in[3];
    const float*         pos  = (const float*)d_in[4];
    const float*         Win  = (const float*)d_in[5];
    const float*         bin  = (const float*)d_in[6];
    const float*         Wout = (const float*)d_in[7];
    const float*         bout = (const float*)d_in[8];
    float* out = (float*)d_out;

    cudaFuncSetAttribute(k_ab, cudaFuncAttributeMaxDynamicSharedMemorySize,
                         (int)sizeof(AbSmem));
    k_ab<<<(Bc * Nc) / CN, 512, sizeof(AbSmem)>>>(ein, mraw, eout, pad, pos,
                                                  Win, bin, Wout, bout);

    // k_cost as programmatic dependent of k_ab
    {
        cudaLaunchConfig_t cfg = {};
        cfg.gridDim  = dim3(Nc / 32, Nc / 32, Bc);
        cfg.blockDim = dim3(256, 1, 1);
        cudaLaunchAttribute attrs[1];
        attrs[0].id = cudaLaunchAttributeProgrammaticStreamSerialization;
        attrs[0].val.programmaticStreamSerializationAllowed = 1;
        cfg.attrs = attrs;
        cfg.numAttrs = 1;
        cudaLaunchKernelEx(&cfg, k_cost);
    }

    // k_sinkhorn as programmatic dependent of k_cost (cluster dims are static)
    cudaFuncSetAttribute(k_sinkhorn, cudaFuncAttributeMaxDynamicSharedMemorySize,
                         (int)sizeof(SmemLayout));
    {
        cudaLaunchConfig_t cfg = {};
        cfg.gridDim  = dim3(Bc * CSZ, 1, 1);
        cfg.blockDim = dim3(TPB, 1, 1);
        cfg.dynamicSmemBytes = sizeof(SmemLayout);
        cudaLaunchAttribute attrs[1];
        attrs[0].id = cudaLaunchAttributeProgrammaticStreamSerialization;
        attrs[0].val.programmaticStreamSerializationAllowed = 1;
        cfg.attrs = attrs;
        cfg.numAttrs = 1;
        cudaLaunchKernelEx(&cfg, k_sinkhorn, out);
    }
}

// round 15
// speedup vs baseline: 1.5392x; 1.0284x over previous
#include <cuda_runtime.h>
#include <cuda_fp16.h>
#include <cooperative_groups.h>

namespace cg = cooperative_groups;

// Problem constants
constexpr int Bc = 8;
constexpr int Nc = 512;
constexpr int Dc = 256;
constexpr int Mc = 32;
constexpr float EPS = 1e-4f;
constexpr int NIT = 2;       // kappa ~ 0.015, d0 ~ 0.01 -> residual ~2e-6 << fp16 floor

// Sinkhorn kernel config
constexpr int CSZ = 8;           // cluster size (CTAs per batch)
constexpr int RPC = Nc / CSZ;    // rows per CTA = 64
constexpr int TPB = 512;         // threads per block (16 warps)

// k_ab config: 16 nodes per block, 256 blocks
constexpr int CN  = 16;          // nodes per block

// PDL helpers (no-ops when kernel not launched as programmatic dependent)
__device__ __forceinline__ void pdl_wait()    { asm volatile("griddepcontrol.wait;" ::: "memory"); }
__device__ __forceinline__ void pdl_trigger() { asm volatile("griddepcontrol.launch_dependents;" ::: "memory"); }

// ---------------- scratch (device globals; no allocation allowed) ----------------
__device__ float  g_a[Bc * Nc * Mc];
__device__ float  g_b[Bc * Nc * Mc];
__device__ __half g_Ch [(size_t)Bc * Nc * Nc];        // 4 MB fp16 raw cost, row-major
__device__ __half g_CTh[(size_t)Bc * Nc * Nc];        // 4 MB fp16 raw cost, transposed
__device__ float  g_sumC[Bc];

extern __shared__ char dynsmem[];

// ---------------- K1: projections; warp-halves split a/b; 16 nodes/block ---------
struct AbSmem {
    float s_in [CN][Dc];       // 16 KB
    float s_out[CN][Dc];       // 16 KB
    float red_a[CN][8][Mc];    // 16 KB
    float red_b[CN][8][Mc];    // 16 KB
    int   s_wb[16];
};

__global__ void __launch_bounds__(512, 2)
k_ab(const float* __restrict__ ein, const unsigned char* __restrict__ mraw,
     const float* __restrict__ eout, const float* __restrict__ pad,
     const float* __restrict__ pos, const float* __restrict__ Win,
     const float* __restrict__ bin, const float* __restrict__ Wout,
     const float* __restrict__ bout)
{
    AbSmem* sm = (AbSmem*)dynsmem;

    int tid  = threadIdx.x;          // 512
    int lane = tid & 31;
    int wid  = tid >> 5;             // 16 warps
    bool isA = wid < 8;
    int seg  = wid & 7;              // 8 segments of 32 d's per projection
    int nb0  = blockIdx.x * CN;      // first node (b*N flat index)

    if (blockIdx.x < Bc && tid == 0) g_sumC[blockIdx.x] = 0.f;

    // ---- issue ALL global loads immediately ----
    unsigned sv = ((const unsigned*)mraw)[tid & 255];      // sniff word (first 1KB)

    float4 i4[2], pd4[2];
    unsigned char mb[2]; int mw[2]; int nds[2], d4s[2];
#pragma unroll
    for (int k = 0; k < 2; k++) {
        int f  = tid + k * 512;
        int nd = f >> 6;                 // node in chunk (0..15)
        int d4 = (f & 63) * 4;           // dim offset
        int bn = nb0 + nd;
        int n  = bn & (Nc - 1);
        nds[k] = nd; d4s[k] = d4;
        float4 a4 = *(const float4*)&eout[(size_t)bn * Dc + d4];
        float4 p4 = *(const float4*)&pos[(size_t)n * Dc + d4];
        a4.x += p4.x; a4.y += p4.y; a4.z += p4.z; a4.w += p4.w;
        *(float4*)&sm->s_out[nd][d4] = a4;            // mask-independent: store now
        i4[k]  = *(const float4*)&ein[(size_t)bn * Dc + d4];
        pd4[k] = *(const float4*)&pad[d4];
        mb[k]  = mraw[bn];                            // bool-layout interpretation
        mw[k]  = ((const int*)mraw)[bn];              // int32-layout interpretation
    }

    float W[32];
    {
        const float* Wsel = isA ? Wout : Win;
        int d0 = seg * 32;
#pragma unroll
        for (int dd = 0; dd < 32; dd++) W[dd] = Wsel[(d0 + dd) * Mc + lane];
    }

    {
        int any = __any_sync(0xffffffffu, (sv & 0xFFFFFF00u) != 0);
        if (lane == 0) sm->s_wb[wid] = any;
    }
    __syncthreads();
    bool isBool = (sm->s_wb[0] | sm->s_wb[1] | sm->s_wb[2]  | sm->s_wb[3]  |
                   sm->s_wb[4] | sm->s_wb[5] | sm->s_wb[6]  | sm->s_wb[7]  |
                   sm->s_wb[8] | sm->s_wb[9] | sm->s_wb[10] | sm->s_wb[11] |
                   sm->s_wb[12]| sm->s_wb[13]| sm->s_wb[14] | sm->s_wb[15]) != 0;

#pragma unroll
    for (int k = 0; k < 2; k++) {
        bool pm = isBool ? (mb[k] != 0) : (mw[k] != 0);
        *(float4*)&sm->s_in[nds[k]][d4s[k]] = pm ? pd4[k] : i4[k];
    }
    __syncthreads();

    {
        const float (*X)[Dc] = isA ? sm->s_out : sm->s_in;
        float (*R)[8][Mc]    = isA ? sm->red_a : sm->red_b;
        int d0 = seg * 32;
#pragma unroll
        for (int nd2 = 0; nd2 < CN; nd2++) {
            float pa = 0.f;
#pragma unroll
            for (int q = 0; q < 8; q++) {
                float4 x = *(const float4*)&X[nd2][d0 + q * 4];
                pa += x.x * W[q*4+0] + x.y * W[q*4+1] + x.z * W[q*4+2] + x.w * W[q*4+3];
            }
            R[nd2][seg][lane] = pa;
        }
    }
    __syncthreads();

    {
        int nd3 = tid >> 5;              // node (0..15)
        int m3  = tid & 31;              // m
        float sa = bout[m3], sb = bin[m3];
#pragma unroll
        for (int sgi = 0; sgi < 8; sgi++) {
            sa += sm->red_a[nd3][sgi][m3];
            sb += sm->red_b[nd3][sgi][m3];
        }
        size_t o = (size_t)(nb0 + nd3) * Mc + m3;
        g_a[o] = sa;
        g_b[o] = sb;
    }
    pdl_trigger();   // after ALL global writes of this CTA
}

// ---------------- K2: C[b,i,j] = sum_m |a[i,m]-b[j,m]| -> fp16 C and C^T + sum ---
__global__ void k_cost()
{
    int b  = blockIdx.z;
    int i0 = blockIdx.y * 32;
    int j0 = blockIdx.x * 32;
    __shared__ float a_s[32][36], b_s[32][36];   // rows 144B: 16B-aligned, odd uint4 stride
    __shared__ float t_s[32][33];
    __shared__ float wsum[8];
    int tid = threadIdx.x;            // 256

    pdl_wait();   // g_a/g_b produced by k_ab

    for (int idx = tid; idx < 1024; idx += 256) {
        int r = idx >> 5, m = idx & 31;
        a_s[r][m] = g_a[((size_t)b * Nc + i0 + r) * Mc + m];
        b_s[r][m] = g_b[((size_t)b * Nc + j0 + r) * Mc + m];
    }
    __syncthreads();

    int j = tid & 31, ig = tid >> 5;
    float acc0 = 0.f, acc1 = 0.f, acc2 = 0.f, acc3 = 0.f;
#pragma unroll
    for (int mq = 0; mq < 8; mq++) {
        float4 bv = *(const float4*)&b_s[j][mq * 4];
        float4 x0 = *(const float4*)&a_s[ig     ][mq * 4];
        float4 x1 = *(const float4*)&a_s[ig +  8][mq * 4];
        float4 x2 = *(const float4*)&a_s[ig + 16][mq * 4];
        float4 x3 = *(const float4*)&a_s[ig + 24][mq * 4];
        acc0 += fabsf(x0.x - bv.x) + fabsf(x0.y - bv.y) + fabsf(x0.z - bv.z) + fabsf(x0.w - bv.w);
        acc1 += fabsf(x1.x - bv.x) + fabsf(x1.y - bv.y) + fabsf(x1.z - bv.z) + fabsf(x1.w - bv.w);
        acc2 += fabsf(x2.x - bv.x) + fabsf(x2.y - bv.y) + fabsf(x2.z - bv.z) + fabsf(x2.w - bv.w);
        acc3 += fabsf(x3.x - bv.x) + fabsf(x3.y - bv.y) + fabsf(x3.z - bv.z) + fabsf(x3.w - bv.w);
    }
    t_s[ig     ][j] = acc0;
    t_s[ig +  8][j] = acc1;
    t_s[ig + 16][j] = acc2;
    t_s[ig + 24][j] = acc3;

    float lsum = (acc0 + acc1) + (acc2 + acc3);
    lsum += __shfl_xor_sync(0xffffffffu, lsum, 16);
    lsum += __shfl_xor_sync(0xffffffffu, lsum, 8);
    lsum += __shfl_xor_sync(0xffffffffu, lsum, 4);
    lsum += __shfl_xor_sync(0xffffffffu, lsum, 2);
    lsum += __shfl_xor_sync(0xffffffffu, lsum, 1);
    if ((tid & 31) == 0) wsum[tid >> 5] = lsum;
    __syncthreads();
    if (tid == 0) {
        float s = 0.f;
#pragma unroll
        for (int w = 0; w < 8; w++) s += wsum[w];
        atomicAdd(&g_sumC[b], s);
    }

    int r  = tid >> 3;
    int c0 = (tid & 7) * 4;
    {
        __half2 h01 = __floats2half2_rn(t_s[r][c0],     t_s[r][c0 + 1]);
        __half2 h23 = __floats2half2_rn(t_s[r][c0 + 2], t_s[r][c0 + 3]);
        size_t cb = ((size_t)b * Nc + i0 + r) * Nc + j0 + c0;
        *(__half2*)&g_Ch[cb]     = h01;
        *(__half2*)&g_Ch[cb + 2] = h23;
    }
    {
        __half2 h01 = __floats2half2_rn(t_s[c0][r],     t_s[c0 + 1][r]);
        __half2 h23 = __floats2half2_rn(t_s[c0 + 2][r], t_s[c0 + 3][r]);
        size_t tb = ((size_t)b * Nc + j0 + r) * Nc + i0 + c0;
        *(__half2*)&g_CTh[tb]     = h01;
        *(__half2*)&g_CTh[tb + 2] = h23;
    }
    pdl_trigger();   // after ALL global writes of this CTA
}

// ---------------- K3: Sinkhorn, 8-CTA cluster, K + K^T resident in SMEM ----------
struct SmemLayout {
    __half Ks [RPC * Nc];    // 64 KB : this CTA's 64 rows of (K-1)
    __half KsT[RPC * Nc];    // 64 KB : this CTA's 64 columns of (K-1) (contiguous after Ks)
    float  c_s[Nc];
    float  r_s[Nc];
    float  r_own[RPC];
    float  c_own[RPC];
    float  rsum[CSZ];
    float  csum[CSZ];
};

__device__ __forceinline__ float warp_sum(float v) {
    v += __shfl_xor_sync(0xffffffffu, v, 16);
    v += __shfl_xor_sync(0xffffffffu, v, 8);
    v += __shfl_xor_sync(0xffffffffu, v, 4);
    v += __shfl_xor_sync(0xffffffffu, v, 2);
    v += __shfl_xor_sync(0xffffffffu, v, 1);
    return v;
}

// 4-row half2 matvec: out[row] = inv_n / (S + sum_j slab[row][j]*vec[j])
__device__ __forceinline__ void matvec4(const __half2* __restrict__ slab2,
                                        const float* __restrict__ vec,
                                        float* __restrict__ outv,
                                        float S, float inv_n, int w, int lane)
{
    float2 vf[8];
    const float2* v2 = (const float2*)vec;
#pragma unroll
    for (int k = 0; k < 8; k++) vf[k] = v2[lane + 32 * k];
#pragma unroll
    for (int rr = 0; rr < 4; rr++) {
        int row = w * 4 + rr;
        const __half2* kr = slab2 + row * (Nc / 2);
        float y = 0.f;
#pragma unroll
        for (int k = 0; k < 8; k++) {
            float2 kf = __half22float2(kr[lane + 32 * k]);
            y += kf.x * vf[k].x + kf.y * vf[k].y;
        }
        y = warp_sum(y);
        if (lane == 0) outv[row] = inv_n / (S + y);
    }
}

__global__ void __cluster_dims__(CSZ, 1, 1) __launch_bounds__(TPB, 1)
k_sinkhorn(float* __restrict__ out)
{
    cg::cluster_group cluster = cg::this_cluster();
    unsigned rank = cluster.block_rank();
    int b = blockIdx.x / CSZ;
    SmemLayout* s = (SmemLayout*)dynsmem;

    int tid  = threadIdx.x;
    int lane = tid & 31;
    int w    = tid >> 5;          // 16 warps
    int jl   = tid & 63;          // column-within-chunk for exchange (RPC=64)
    int dstR = tid >> 6;          // destination rank for exchange (0..7)

    // independent prologue before the PDL wait
    s->c_s[tid] = 1.0f;                         // c0 = 1
    if (tid < CSZ) s->csum[tid] = (float)RPC;   // each rank's c-chunk sums to 64

    pdl_wait();   // g_Ch/g_CTh/g_sumC produced by k_cost

    // Load raw-C row slab + column slab (64 KB each), linear int4 copies
    {
        const int4* srcR_ = (const int4*)(g_Ch  + ((size_t)b * Nc + rank * RPC) * Nc);
        const int4* srcT  = (const int4*)(g_CTh + ((size_t)b * Nc + rank * RPC) * Nc);
        int4* dR = (int4*)s->Ks;
        int4* dT = (int4*)s->KsT;
#pragma unroll
        for (int t = tid; t < RPC * Nc * 2 / 16; t += TPB) { dR[t] = srcR_[t]; dT[t] = srcT[t]; }
    }
    __syncthreads();

    // In-place convert: Kp = expm1(-C*inv), half2 Taylor (covers Ks+KsT contiguously)
    {
        float inv = 1.f / (EPS * g_sumC[b]);
        __half2 ninv2 = __float2half2_rn(-inv);
        const __half2 c4 = __float2half2_rn(1.f / 24.f);
        const __half2 c3 = __float2half2_rn(1.f / 6.f);
        const __half2 c2 = __float2half2_rn(0.5f);
        const __half2 c1 = __float2half2_rn(1.0f);
        __half2* p = (__half2*)s->Ks;    // RPC*Nc half2 = both 64KB slabs
#pragma unroll
        for (int t = tid; t < RPC * Nc; t += TPB) {
            __half2 x = __hmul2(p[t], ninv2);
            __half2 q = __hfma2(x, c4, c3);
            q = __hfma2(x, q, c2);
            q = __hfma2(x, q, c1);
            p[t] = __hmul2(x, q);
        }
    }
    __syncthreads();

    const float inv_n = 1.0f / (float)Nc;
    const __half2* Ks2  = (const __half2*)s->Ks;
    const __half2* KsT2 = (const __half2*)s->KsT;

    float* remote_r = (float*)cluster.map_shared_rank(s->r_s, dstR) + rank * RPC + jl;
    float* remote_c = (float*)cluster.map_shared_rank(s->c_s, dstR) + rank * RPC + jl;

    for (int it = 0; it < NIT; it++) {
        // ---- Phase A: r_own = inv_n / (S_c + Kp_rows . c) ----
        float S_c = ((s->csum[0] + s->csum[1]) + (s->csum[2] + s->csum[3]))
                  + ((s->csum[4] + s->csum[5]) + (s->csum[6] + s->csum[7]));
        matvec4(Ks2, s->c_s, s->r_own, S_c, inv_n, w, lane);
        __syncthreads();

        // chunk partial sum -> all ranks' rsum; broadcast r_own -> all ranks' r_s
        if (w == 0) {
            float v = warp_sum(s->r_own[lane] + s->r_own[lane + 32]);
            if (lane < CSZ)
                ((float*)cluster.map_shared_rank(s->rsum, lane))[rank] = v;
        }
        *remote_r = s->r_own[jl];
        cluster.sync();

        // ---- Phase B: c_own = inv_n / (S_r + Kp_cols . r) ----
        float S_r = ((s->rsum[0] + s->rsum[1]) + (s->rsum[2] + s->rsum[3]))
                  + ((s->rsum[4] + s->rsum[5]) + (s->rsum[6] + s->rsum[7]));
        matvec4(KsT2, s->r_s, s->c_own, S_r, inv_n, w, lane);
        __syncthreads();

        if (w == 0) {
            float v = warp_sum(s->c_own[lane] + s->c_own[lane + 32]);
            if (lane < CSZ)
                ((float*)cluster.map_shared_rank(s->csum, lane))[rank] = v;
        }
        *remote_c = s->c_own[jl];
        cluster.sync();
    }

    // ---- epilogue: P[b,i,j] = (1 + Kp[i,j]) * r_i * c_j ----
    float* Ob = out + ((size_t)b * Nc + rank * RPC) * Nc;
#pragma unroll
    for (int rr = 0; rr < 4; rr++) {
        int row = w * 4 + rr;
        float rv = s->r_own[row];
        float* orow = Ob + (size_t)row * Nc;
        const __half2* kr = (const __half2*)s->Ks + row * (Nc / 2);
        const float2* c2 = (const float2*)s->c_s;
#pragma unroll
        for (int k = 0; k < 8; k++) {
            float2 kf = __half22float2(kr[lane + 32 * k]);
            float2 cf = c2[lane + 32 * k];
            float2 o;
            o.x = (1.0f + kf.x) * rv * cf.x;
            o.y = (1.0f + kf.y) * rv * cf.y;
            *(float2*)&orow[2 * (lane + 32 * k)] = o;
        }
    }
}

// ---------------- launcher -------------------------------------------------------
extern "C" void kernel_launch(void* const* d_in, const int* in_sizes, int n_in,
                              void* d_out, int out_size)
{
    const float*         ein  = (const float*)d_in[0];
    const unsigned char* mraw = (const unsigned char*)d_in[1];   // bool OR int32, sniffed
    const float*         eout = (const float*)d_in[2];
    const float*         pad  = (const float*)d_in[3];
    const float*         pos  = (const float*)d_in[4];
    const float*         Win  = (const float*)d_in[5];
    const float*         bin  = (const float*)d_in[6];
    const float*         Wout = (const float*)d_in[7];
    const float*         bout = (const float*)d_in[8];
    float* out = (float*)d_out;

    cudaFuncSetAttribute(k_ab, cudaFuncAttributeMaxDynamicSharedMemorySize,
                         (int)sizeof(AbSmem));
    k_ab<<<(Bc * Nc) / CN, 512, sizeof(AbSmem)>>>(ein, mraw, eout, pad, pos,
                                                  Win, bin, Wout, bout);

    // k_cost as programmatic dependent of k_ab
    {
        cudaLaunchConfig_t cfg = {};
        cfg.gridDim  = dim3(Nc / 32, Nc / 32, Bc);
        cfg.blockDim = dim3(256, 1, 1);
        cudaLaunchAttribute attrs[1];
        attrs[0].id = cudaLaunchAttributeProgrammaticStreamSerialization;
        attrs[0].val.programmaticStreamSerializationAllowed = 1;
        cfg.attrs = attrs;
        cfg.numAttrs = 1;
        cudaLaunchKernelEx(&cfg, k_cost);
    }

    // k_sinkhorn as programmatic dependent of k_cost (cluster dims are static)
    cudaFuncSetAttribute(k_sinkhorn, cudaFuncAttributeMaxDynamicSharedMemorySize,
                         (int)sizeof(SmemLayout));
    {
        cudaLaunchConfig_t cfg = {};
        cfg.gridDim  = dim3(Bc * CSZ, 1, 1);
        cfg.blockDim = dim3(TPB, 1, 1);
        cfg.dynamicSmemBytes = sizeof(SmemLayout);
        cudaLaunchAttribute attrs[1];
        attrs[0].id = cudaLaunchAttributeProgrammaticStreamSerialization;
        attrs[0].val.programmaticStreamSerializationAllowed = 1;
        cfg.attrs = attrs;
        cfg.numAttrs = 1;
        cudaLaunchKernelEx(&cfg, k_sinkhorn, out);
    }
}